// round 8
// baseline (speedup 1.0000x reference)
#include <cuda_runtime.h>
#include <math.h>
#include <stdint.h>

#define Bn 64
#define Tn 512
#define Xn 8
#define Hn 128
#define K3 384   // 3*H
#define HB 64    // half of H

typedef unsigned long long ull;

// -------- device scratch (allocation-free) --------
__device__ float g_Pw[(size_t)Bn * Tn * Xn * K3];  // [B,T,X,3H]
__device__ float g_Pc[(size_t)Bn * Tn * K3];       // [B,T,3H]
__device__ float g_Pa[(size_t)Bn * Tn * Hn];       // [B,T,H]
__device__ float g_proj[(size_t)Bn * Tn * K3];     // proj[b][s] = h1(s) @ w_hh_w

// -------- asm helpers --------
__device__ __forceinline__ void cpa16(uint32_t s, const void* g) {
    asm volatile("cp.async.cg.shared.global [%0], [%1], 16;" :: "r"(s), "l"(g));
}
__device__ __forceinline__ void cp_commit() { asm volatile("cp.async.commit_group;"); }
template<int N> __device__ __forceinline__ void cp_wait() {
    asm volatile("cp.async.wait_group %0;" :: "n"(N));
}
__device__ __forceinline__ ull pk2(float x, float y) {
    ull r; asm("mov.b64 %0, {%1, %2};" : "=l"(r) : "f"(x), "f"(y)); return r;
}
__device__ __forceinline__ void upk2(ull v, float& x, float& y) {
    asm("mov.b64 {%0, %1}, %2;" : "=f"(x), "=f"(y) : "l"(v));
}
__device__ __forceinline__ ull fma2(ull a, ull b, ull c) {
    ull d; asm("fma.rn.f32x2 %0, %1, %2, %3;" : "=l"(d) : "l"(a), "l"(b), "l"(c));
    return d;
}
__device__ __forceinline__ ull add2(ull a, ull b) {
    ull d; asm("add.rn.f32x2 %0, %1, %2;" : "=l"(d) : "l"(a), "l"(b));
    return d;
}
__device__ __forceinline__ uint32_t smem_u32(const void* p) {
    return (uint32_t)__cvta_generic_to_shared(p);
}
__device__ __forceinline__ uint32_t mapa_u32(uint32_t a, uint32_t rank) {
    uint32_t d;
    asm("mapa.shared::cluster.u32 %0, %1, %2;" : "=r"(d) : "r"(a), "r"(rank));
    return d;
}
__device__ __forceinline__ void st_cluster_f2(uint32_t a, float x, float y) {
    asm volatile("st.shared::cluster.v2.f32 [%0], {%1, %2};"
                 :: "r"(a), "f"(x), "f"(y) : "memory");
}
__device__ __forceinline__ void st_cluster_u64(uint32_t a, ull v) {
    asm volatile("st.shared::cluster.u64 [%0], %1;" :: "r"(a), "l"(v) : "memory");
}
__device__ __forceinline__ void mbar_init(uint32_t a, uint32_t cnt) {
    asm volatile("mbarrier.init.shared.b64 [%0], %1;" :: "r"(a), "r"(cnt) : "memory");
}
__device__ __forceinline__ void mbar_arrive_remote(uint32_t ra) {
    asm volatile("mbarrier.arrive.release.cluster.shared::cluster.b64 _, [%0];"
                 :: "r"(ra) : "memory");
}
__device__ __forceinline__ void mbar_wait(uint32_t a, uint32_t parity) {
    asm volatile(
        "{\n\t.reg .pred P1;\n\t"
        "WL%=:\n\t"
        "mbarrier.try_wait.parity.acquire.cluster.shared::cta.b64 P1, [%0], %1;\n\t"
        "@!P1 bra WL%=;\n\t"
        "}"
        :: "r"(a), "r"(parity) : "memory");
}
#define CLUSTER_ARRIVE() asm volatile("barrier.cluster.arrive.aligned;" ::: "memory")
#define CLUSTER_WAIT()   asm volatile("barrier.cluster.wait.aligned;"   ::: "memory")

__device__ __forceinline__ float sigm(float x) { return 1.f / (1.f + __expf(-x)); }
__device__ __forceinline__ float tanh_(float x) {
    float e = __expf(2.f * x);
    return 1.f - 2.f / (e + 1.f);
}

// ---------------------------------------------------------------------
// SGEMM (unchanged)
// ---------------------------------------------------------------------
__global__ __launch_bounds__(256) void gemm128(
    const float* __restrict__ A, const float* __restrict__ W,
    const float* __restrict__ bias, float* __restrict__ C, int N)
{
    __shared__ float As[2][8][128];
    __shared__ float Bs[2][8][128];

    const int tid = threadIdx.x;
    const int m0 = blockIdx.y * 128;
    const int n0 = blockIdx.x * 128;

    const int arow = tid >> 1;
    const int ak4  = (tid & 1) << 2;
    const int brow = tid >> 5;
    const int bc4  = (tid & 31) << 2;
    const int ty   = tid >> 4;
    const int tx   = tid & 15;

    const float* Ag = A + (size_t)(m0 + arow) * 128 + ak4;
    const float* Wg = W + (size_t)brow * N + n0 + bc4;

    ull acc2[8][4];
#pragma unroll
    for (int i = 0; i < 8; i++)
#pragma unroll
        for (int j = 0; j < 4; j++) acc2[i][j] = 0ull;

    float4 ra = *(const float4*)Ag;
    float4 rb = *(const float4*)Wg;
    As[0][ak4 + 0][arow] = ra.x; As[0][ak4 + 1][arow] = ra.y;
    As[0][ak4 + 2][arow] = ra.z; As[0][ak4 + 3][arow] = ra.w;
    *(float4*)&Bs[0][brow][bc4] = rb;
    __syncthreads();

    int p = 0;
    for (int kc = 8; kc <= 128; kc += 8) {
        const bool more = (kc < 128);
        if (more) {
            ra = *(const float4*)(Ag + kc);
            rb = *(const float4*)(Wg + (size_t)kc * N);
        }
#pragma unroll
        for (int k = 0; k < 8; k++) {
            float af[8], bf[8];
            *(float4*)&af[0] = *(const float4*)&As[p][k][ty * 4];
            *(float4*)&af[4] = *(const float4*)&As[p][k][ty * 4 + 64];
            *(float4*)&bf[0] = *(const float4*)&Bs[p][k][tx * 4];
            *(float4*)&bf[4] = *(const float4*)&Bs[p][k][tx * 4 + 64];
            ull bd[4];
            bd[0] = pk2(bf[0], bf[1]); bd[1] = pk2(bf[2], bf[3]);
            bd[2] = pk2(bf[4], bf[5]); bd[3] = pk2(bf[6], bf[7]);
#pragma unroll
            for (int i = 0; i < 8; i++) {
                ull ad = pk2(af[i], af[i]);
#pragma unroll
                for (int j = 0; j < 4; j++) acc2[i][j] = fma2(ad, bd[j], acc2[i][j]);
            }
        }
        if (more) {
            p ^= 1;
            As[p][ak4 + 0][arow] = ra.x; As[p][ak4 + 1][arow] = ra.y;
            As[p][ak4 + 2][arow] = ra.z; As[p][ak4 + 3][arow] = ra.w;
            *(float4*)&Bs[p][brow][bc4] = rb;
            __syncthreads();
        }
    }

    float bv[8];
#pragma unroll
    for (int j = 0; j < 4; j++) {
        bv[j]     = bias[n0 + tx * 4 + j];
        bv[j + 4] = bias[n0 + tx * 4 + 64 + j];
    }
#pragma unroll
    for (int i = 0; i < 8; i++) {
        const int r = m0 + ty * 4 + (i & 3) + ((i >> 2) << 6);
        float a0, a1, a2, a3, a4, a5, a6, a7;
        upk2(acc2[i][0], a0, a1); upk2(acc2[i][1], a2, a3);
        upk2(acc2[i][2], a4, a5); upk2(acc2[i][3], a6, a7);
        float4 o0, o1;
        o0.x = a0 + bv[0]; o0.y = a1 + bv[1]; o0.z = a2 + bv[2]; o0.w = a3 + bv[3];
        o1.x = a4 + bv[4]; o1.y = a5 + bv[5]; o1.z = a6 + bv[6]; o1.w = a7 + bv[7];
        *(float4*)&C[(size_t)r * N + n0 + tx * 4]      = o0;
        *(float4*)&C[(size_t)r * N + n0 + tx * 4 + 64] = o1;
    }
}

// ---------------------------------------------------------------------
// Recurrent scan: 2-CTA cluster per batch, COLUMN-split matvec.
// ---------------------------------------------------------------------
struct PFB {                      // per-step prefetch buffers (double buffered)
    float cx[Xn][HB];             // 2048  (offset 0)
    float pr[Xn][3][HB];          // 6144  (offset 2048)
    float pw[Xn][3][HB];          // 6144  (offset 8192)
    float pa[HB];                 //  256  (offset 14336)
};

struct alignas(16) RecSmem {
    ulonglong2 wsm2[8][384];      // 49152: weight rows 96..127 (k-pairs x2) per thread-col
    ull   ahh2[Hn][HB / 2];       // 32768: a_hh[:, own half] packed as h-pairs
    float c1s[Xn][132];           //  4224 (padded stride vs bank conflicts)
    float projw[K3];              //  1536 (own 192 cols valid)
    float gc[K3];                 //  1536 (own 192 cols valid)
    ull   epart[2][8][34];        //  4352: alpha partials [khalf][x][h-pair]
    float2 eal[Xn][HB / 2];       //  2048: exp(alpha)
    float2 eca[Xn][HB / 2];       //  2048: c1s * exp(alpha)
    PFB   pfb[2];                 // 29184
    float ig[HB], og[HB], gg[HB]; //   768
    float cprev[HB];              //   256
    ull   h1p[64];                //   512: FULL h1 as packed pairs
    int   jsb[2][9];              // js[0..7] + cn at [8]
    ull   mbar[2];                // [0]=c1s, [1]=h1
};

__global__ __launch_bounds__(384, 1) __cluster_dims__(2, 1, 1)
void lattice_recurrent(
    const float* __restrict__ whhw,   // [128,384]
    const float* __restrict__ whhc,   // [128,384]
    const float* __restrict__ ahh_g,  // [128,128]
    const int*   __restrict__ srcp,   // [B,T,X]
    const int*   __restrict__ cntp,   // [B,T]
    float* __restrict__ out)          // hs then cs, each [B,T,H]
{
    extern __shared__ unsigned char smem_raw[];
    RecSmem& sm = *reinterpret_cast<RecSmem*>(smem_raw);

    const int rank = blockIdx.x & 1;
    const int b    = blockIdx.x >> 1;
    const int peer = rank ^ 1;
    const int tid  = threadIdx.x;
    const int bx   = tid >> 5;
    const int lane = tid & 31;
    const int k0   = rank * HB;

    float* hs = out;
    float* cs = out + (size_t)Bn * Tn * Hn;

    // ---- own output column (col-split): tid<192 -> projw, else -> gc ----
    const int jcol = (tid < 192) ? tid : tid - 192;
    const int gcol = ((jcol >> 6) << 7) + k0 + (jcol & 63);
    const float* Wmat = (tid < 192) ? whhw : whhc;

    // ---- one-time init ----
    if (tid == 0) {
        mbar_init(smem_u32(&sm.mbar[0]), 1);
        mbar_init(smem_u32(&sm.mbar[1]), 1);
    }
    // weight rows 0..95 into regs (48 k-pair packs)
    ull wr2[48];
#pragma unroll
    for (int i = 0; i < 48; i++)
        wr2[i] = pk2(Wmat[(size_t)(2 * i) * K3 + gcol],
                     Wmat[(size_t)(2 * i + 1) * K3 + gcol]);
    // rows 96..127 into smem (per thread-col, 8 x ulonglong2)
#pragma unroll
    for (int r = 0; r < 8; r++) {
        ulonglong2 v;
        v.x = pk2(Wmat[(size_t)(96 + 4 * r) * K3 + gcol],
                  Wmat[(size_t)(97 + 4 * r) * K3 + gcol]);
        v.y = pk2(Wmat[(size_t)(98 + 4 * r) * K3 + gcol],
                  Wmat[(size_t)(99 + 4 * r) * K3 + gcol]);
        sm.wsm2[r][tid] = v;
    }
    // ahh own columns, packed h-pairs
    for (int i = tid; i < Hn * (HB / 2); i += 384) {
        int k = i / (HB / 2), p = i % (HB / 2);
        sm.ahh2[k][p] = pk2(ahh_g[(size_t)k * Hn + k0 + 2 * p],
                            ahh_g[(size_t)k * Hn + k0 + 2 * p + 1]);
    }
    if (tid < 8)       sm.jsb[0][tid] = srcp[(b * Tn) * Xn + tid];
    else if (tid == 8) sm.jsb[0][8]   = cntp[b * Tn];
    __syncthreads();
    CLUSTER_ARRIVE(); CLUSTER_WAIT();   // peer mbars + weights ready

    // ---- hoisted cluster addresses ----
    const int h2 = 2 * lane;
    const int hg = k0 + h2;
    const uint32_t c1s_peer = (bx < 8)
        ? mapa_u32(smem_u32(&sm.c1s[bx][hg]), peer) : 0u;
    const uint32_t h1p_peer = mapa_u32(smem_u32(&sm.h1p[(k0 >> 1) + lane]), peer);
    const uint32_t mb0_l = smem_u32(&sm.mbar[0]);
    const uint32_t mb1_l = smem_u32(&sm.mbar[1]);
    const uint32_t mb0_p = mapa_u32(mb0_l, peer);
    const uint32_t mb1_p = mapa_u32(mb1_l, peer);
    const uint32_t pfb_base[2] = { smem_u32(&sm.pfb[0]), smem_u32(&sm.pfb[1]) };

    // ---- hoisted prefetch slot decode (3 slots per thread) ----
    const float*   pf_q[3];
    uint32_t       pf_rel[3];
    int            pf_x[3], pf_st[3];
    long           pf_adv[3];
    bool           pf_v[3];
#pragma unroll
    for (int si = 0; si < 3; si++) {
        int s = tid + si * 384;
        pf_v[si] = (s < 912);
        pf_q[si] = nullptr; pf_rel[si] = 0; pf_x[si] = 0; pf_st[si] = 0; pf_adv[si] = 0;
        if (s < 128) {                      // cx gather
            int x = s >> 4, c = (s & 15) << 2;
            pf_rel[si] = (uint32_t)((x * 64 + c) * 4);
            pf_q[si]   = cs + (size_t)b * Tn * Hn + k0 + c;
            pf_x[si] = x; pf_st[si] = Hn;
        } else if (s < 512) {               // proj gather
            int r = s - 128, u = r >> 4, c = (r & 15) << 2;
            int x = u / 3, g = u - x * 3;
            pf_rel[si] = 2048u + (uint32_t)((u * 64 + c) * 4);
            pf_q[si]   = g_proj + (size_t)b * Tn * K3 + g * 128 + k0 + c;
            pf_x[si] = x; pf_st[si] = K3;
        } else if (s < 896) {               // Pw (running per-t pointer)
            int r = s - 512, u = r >> 4, c = (r & 15) << 2;
            int x = u / 3, g = u - x * 3;
            pf_rel[si] = 8192u + (uint32_t)((u * 64 + c) * 4);
            pf_q[si]   = g_Pw + (size_t)b * Tn * Xn * K3 + (size_t)x * K3
                       + g * 128 + k0 + c;
            pf_adv[si] = (long)Xn * K3;
        } else if (s < 912) {               // Pa (running)
            int c = (s - 896) << 2;
            pf_rel[si] = 14336u + (uint32_t)(c * 4);
            pf_q[si]   = g_Pa + (size_t)b * Tn * Hn + k0 + c;
            pf_adv[si] = Hn;
        }
    }

    // ---- prologue prefetch for t=0 into pfb[0] ----
#pragma unroll
    for (int si = 0; si < 3; si++) {
        if (pf_v[si]) {
            const float* p = pf_q[si];
            if (pf_st[si]) p += (size_t)sm.jsb[0][pf_x[si]] * pf_st[si];
            cpa16(pfb_base[0] + pf_rel[si], p);
        }
    }
    cp_commit();

    for (int t = 0; t < Tn; t++) {
        const int pb = t & 1;
        const size_t bT = (size_t)b * Tn + t;
        const int cn = sm.jsb[pb][8];

        // early independent LDGs
        float pc = 0.f;
        if (tid >= 192) pc = g_Pc[bT * K3 + gcol];
        int jv = 0;
        if (t + 1 < Tn && tid >= 320 && tid < 329)
            jv = (tid < 328) ? srcp[(bT + 1) * Xn + (tid - 320)] : cntp[bT + 1];

        // h1 ready? (exchange from step t-1)
        if (t > 0) {
            if (tid == 0) mbar_arrive_remote(mb1_p);
            mbar_wait(mb1_l, (t - 1) & 1);
        }

        // ---- phase A: full-k matvec for own column ----
        float val = 0.f;
        if (t > 0) {
            const ulonglong2* h1q = (const ulonglong2*)sm.h1p;
            ull a0 = 0, a1 = 0, a2 = 0, a3 = 0;
#pragma unroll
            for (int i = 0; i < 24; i++) {
                ulonglong2 hv = h1q[i];
                if (i & 1) { a2 = fma2(hv.x, wr2[2 * i], a2);
                             a3 = fma2(hv.y, wr2[2 * i + 1], a3); }
                else       { a0 = fma2(hv.x, wr2[2 * i], a0);
                             a1 = fma2(hv.y, wr2[2 * i + 1], a1); }
            }
#pragma unroll
            for (int r = 0; r < 8; r++) {
                ulonglong2 wv = sm.wsm2[r][tid];
                ulonglong2 hv = h1q[24 + r];
                if (r & 1) { a2 = fma2(hv.x, wv.x, a2);
                             a3 = fma2(hv.y, wv.y, a3); }
                else       { a0 = fma2(hv.x, wv.x, a0);
                             a1 = fma2(hv.y, wv.y, a1); }
            }
            ull s = add2(add2(a0, a2), add2(a1, a3));
            float lo, hi; upk2(s, lo, hi);
            val = lo + hi;
        }
        if (tid < 192) {
            sm.projw[gcol] = val;
            if (t > 0) g_proj[(bT - 1) * K3 + gcol] = val;
        } else {
            sm.gc[gcol] = val + pc;
        }

        cp_wait<0>();          // this step's prefetched buffers landed
        __syncthreads();       // sync1: projw/gc + buffers visible

        // ---- phase B: c1_skip (warps 0..7, x<cn) + gates + jsb staging ----
        if (bx < 8) {
            const int x = bx;
            if (x < cn) {
                const int s = sm.jsb[pb][x];
                const bool prev = (s == t - 1);
                const PFB& pf = sm.pfb[pb];
                float2 r0 = prev ? *(const float2*)&sm.projw[hg]
                                 : *(const float2*)&pf.pr[x][0][h2];
                float2 r1 = prev ? *(const float2*)&sm.projw[hg + 128]
                                 : *(const float2*)&pf.pr[x][1][h2];
                float2 r2 = prev ? *(const float2*)&sm.projw[hg + 256]
                                 : *(const float2*)&pf.pr[x][2][h2];
                float2 w0 = *(const float2*)&pf.pw[x][0][h2];
                float2 w1 = *(const float2*)&pf.pw[x][1][h2];
                float2 w2 = *(const float2*)&pf.pw[x][2][h2];
                float2 cx = prev ? *(const float2*)&sm.cprev[h2]
                                 : *(const float2*)&pf.cx[x][h2];
                float c1a, c1b;
                {
                    const float fg = sigm(r0.x + w0.x);
                    const float iw = sigm(r1.x + w1.x);
                    const float gv = tanh_(r2.x + w2.x);
                    c1a = fg * cx.x + iw * gv;
                }
                {
                    const float fg = sigm(r0.y + w0.y);
                    const float iw = sigm(r1.y + w1.y);
                    const float gv = tanh_(r2.y + w2.y);
                    c1b = fg * cx.y + iw * gv;
                }
                *(float2*)&sm.c1s[x][hg] = make_float2(c1a, c1b);
                st_cluster_f2(c1s_peer, c1a, c1b);
            }
        } else if (tid < 320) {
            const int j = tid - 256;
            sm.ig[j] = sigm(sm.gc[k0 + j]);
            sm.og[j] = sigm(sm.gc[k0 + j + 128]);
            sm.gg[j] = tanh_(sm.gc[k0 + j + 256]);
        } else if (tid < 329 && t + 1 < Tn) {
            sm.jsb[pb ^ 1][tid - 320] = jv;
        }
        __syncthreads();       // sync2
        if (tid == 0) mbar_arrive_remote(mb0_p);
        mbar_wait(mb0_l, t & 1);

        // ---- issue NEXT step's prefetch (buffers now free; jsb staged) ----
        if (t + 1 < Tn) {
            const int nb = pb ^ 1;
#pragma unroll
            for (int si = 0; si < 3; si++) {
                if (pf_v[si]) {
                    pf_q[si] += pf_adv[si];
                    const float* p = pf_q[si];
                    if (pf_st[si]) p += (size_t)sm.jsb[nb][pf_x[si]] * pf_st[si];
                    cpa16(pfb_base[nb] + pf_rel[si], p);
                }
            }
        }
        cp_commit();

        // ---- phase E1: alpha partials, broadcast layout (warps 0..7) ----
        if (bx < 8) {
            const int kh = bx >> 2, w4 = bx & 3;
            const int x  = lane >> 2, hq = lane & 3;
            const int h4 = w4 * 16 + hq * 4;
            const int kb = kh * 64;
            ull p01 = 0, p23 = 0, q01 = 0, q23 = 0;
#pragma unroll 16
            for (int k = 0; k < 64; k += 2) {
                ulonglong2 av0 = *(const ulonglong2*)&sm.ahh2[kb + k][h4 >> 1];
                ulonglong2 av1 = *(const ulonglong2*)&sm.ahh2[kb + k + 1][h4 >> 1];
                float2 cv = *(const float2*)&sm.c1s[x][kb + k];
                ull c0 = pk2(cv.x, cv.x), c1 = pk2(cv.y, cv.y);
                p01 = fma2(c0, av0.x, p01);
                p23 = fma2(c0, av0.y, p23);
                q01 = fma2(c1, av1.x, q01);
                q23 = fma2(c1, av1.y, q23);
            }
            const int pidx = w4 * 8 + hq * 2;
            sm.epart[kh][x][pidx]     = add2(p01, q01);
            sm.epart[kh][x][pidx + 1] = add2(p23, q23);
        }
        __syncthreads();       // sync3

        // ---- phase E2: reduce + sigmoid + exp (256 threads, x<cn skip) ----
        if (tid < 256) {
            const int x = tid >> 5, p = tid & 31;
            if (x < cn) {
                ull s2 = add2(sm.epart[0][x][p], sm.epart[1][x][p]);
                float2 pa = *(const float2*)&sm.pfb[pb].pa[2 * p];
                float a0, a1; upk2(s2, a0, a1);
                a0 = sigm(a0 + pa.x);
                a1 = sigm(a1 + pa.y);
                float e0 = __expf(a0), e1 = __expf(a1);
                sm.eal[x][p] = make_float2(e0, e1);
                float2 cv = *(const float2*)&sm.c1s[x][k0 + 2 * p];
                sm.eca[x][p] = make_float2(cv.x * e0, cv.y * e1);
            }
        }
        __syncthreads();       // sync4

        // ---- phase F: merge (warp 0), write out, send h1 pair to peer ----
        if (bx == 0) {
            const int j2 = h2;
            const float e0a = __expf(sm.ig[j2]);
            const float e0b = __expf(sm.ig[j2 + 1]);
            float dena = e0a, denb = e0b;
            float numa = sm.gg[j2] * e0a, numb = sm.gg[j2 + 1] * e0b;
#pragma unroll
            for (int x = 0; x < 8; x++) {
                if (x < cn) {
                    float2 ea = sm.eal[x][lane];
                    float2 ec = sm.eca[x][lane];
                    dena += ea.x; denb += ea.y;
                    numa += ec.x; numb += ec.y;
                }
            }
            const float c1a = numa / dena;
            const float c1b = numb / denb;
            const float h1a = sm.og[j2]     * tanh_(c1a);
            const float h1b = sm.og[j2 + 1] * tanh_(c1b);
            *(float2*)&hs[bT * Hn + k0 + j2] = make_float2(h1a, h1b);
            *(float2*)&cs[bT * Hn + k0 + j2] = make_float2(c1a, c1b);
            sm.cprev[j2]     = c1a;
            sm.cprev[j2 + 1] = c1b;
            const ull hp = pk2(h1a, h1b);
            sm.h1p[(k0 >> 1) + lane] = hp;
            st_cluster_u64(h1p_peer, hp);
        }
        __syncthreads();       // sync5: orders F stores before next arrive
    }
}

// ---------------------------------------------------------------------
extern "C" void kernel_launch(void* const* d_in, const int* in_sizes, int n_in,
                              void* d_out, int out_size)
{
    int i_src, i_cnt, i_wihc, i_whhc, i_bc, i_aih, i_ahh, i_ab, i_wihw, i_whhw, i_bw;
    if (in_sizes[2] == Bn) {
        i_src = 3;  i_cnt = 4;
        i_wihc = 5; i_whhc = 6; i_bc = 7;
        i_aih = 8;  i_ahh = 9;  i_ab = 10;
        i_wihw = 11; i_whhw = 12; i_bw = 13;
    } else {
        i_wihc = 2; i_whhc = 3; i_bc = 4;
        i_aih = 5;  i_ahh = 6;  i_ab = 7;
        i_wihw = 8; i_whhw = 9; i_bw = 10;
        i_src = 12; i_cnt = 13;
    }

    const float* inp        = (const float*)d_in[0];
    const float* skip_words = (const float*)d_in[1];
    const int*   srcp       = (const int*)d_in[i_src];
    const int*   cntp       = (const int*)d_in[i_cnt];
    const float* wihc = (const float*)d_in[i_wihc];
    const float* whhc = (const float*)d_in[i_whhc];
    const float* bc   = (const float*)d_in[i_bc];
    const float* aih  = (const float*)d_in[i_aih];
    const float* ahh  = (const float*)d_in[i_ahh];
    const float* ab   = (const float*)d_in[i_ab];
    const float* wihw = (const float*)d_in[i_wihw];
    const float* whhw = (const float*)d_in[i_whhw];
    const float* bw   = (const float*)d_in[i_bw];

    float *Pw, *Pc, *Pa;
    cudaGetSymbolAddress((void**)&Pw, g_Pw);
    cudaGetSymbolAddress((void**)&Pc, g_Pc);
    cudaGetSymbolAddress((void**)&Pa, g_Pa);

    // Input projections
    gemm128<<<dim3(K3 / 128, (Bn * Tn * Xn) / 128), 256>>>(skip_words, wihw, bw, Pw, K3);
    gemm128<<<dim3(K3 / 128, (Bn * Tn) / 128),      256>>>(inp,        wihc, bc, Pc, K3);
    gemm128<<<dim3(Hn / 128, (Bn * Tn) / 128),      256>>>(inp,        aih,  ab, Pa, Hn);

    static int attr_done = 0;
    if (!attr_done) {
        cudaFuncSetAttribute(lattice_recurrent,
                             cudaFuncAttributeMaxDynamicSharedMemorySize,
                             (int)sizeof(RecSmem));
        attr_done = 1;
    }
    lattice_recurrent<<<Bn * 2, 384, sizeof(RecSmem)>>>(whhw, whhc, ahh,
                                                        srcp, cntp, (float*)d_out);
}